// round 16
// baseline (speedup 1.0000x reference)
#include <cuda_runtime.h>
#include <cuda_bf16.h>
#include <cstdint>

#define NB 4
#define NN 1024
#define AIN 8
#define AOUT 16
#define XIN 64
#define XOUT 64

typedef unsigned long long ULL;

// ---------------- scratch (device globals; no allocation) ----------------
__device__ float g_moc[NB*NN*AIN];
__device__ float g_dp [NB*NN*AIN];
__device__ float g_mdp[NB*AIN];
__device__ float g_mall[NB*AIN];
__device__ float g_mX [NB*XIN];
__device__ float g_C  [NB*AOUT];
__device__ float g_R  [NB*NN*AOUT];
__device__ float g_Rt [NB*AOUT*NN];      // R transposed: [n][s][j]
__device__ float g_X1t[NB*NN*XOUT];
__device__ float g_X2t[NB*NN*XOUT];
__device__ __align__(16) __nv_bfloat16 g_X2tT_hi[NB*XOUT*NN];   // [n][t][j]
__device__ __align__(16) __nv_bfloat16 g_X2tT_lo[NB*XOUT*NN];   // [n][t][j]
__device__ float g_T  [NB*AOUT*XOUT];
__device__ float g_K  [NB*XOUT];
__device__ float g_OWH[AIN*XOUT*XOUT];
__device__ __align__(16) float g_H[NB*NN*AIN*XOUT];
__device__ float g_Qpart[NB*16*AOUT*XOUT];
__device__ float g_SX2part[NB*16*XOUT];

#define FMA2(d,a,b) asm("fma.rn.f32x2 %0, %1, %2, %0;" : "+l"(d) : "l"(a), "l"(b))
#define PACK2(d,x)  asm("mov.b64 %0, {%1, %1};" : "=l"(d) : "f"(x))
#define PACKXY(d,x,y) asm("mov.b64 %0, {%1, %2};" : "=l"(d) : "f"(x), "f"(y))
#define UNPACK2(lo,hi,d) asm("mov.b64 {%0, %1}, %2;" : "=f"(lo), "=f"(hi) : "l"(d))

#define LDSM_X4(r0,r1,r2,r3,addr) \
    asm volatile("ldmatrix.sync.aligned.m8n8.x4.shared.b16 {%0,%1,%2,%3}, [%4];" \
        : "=r"(r0),"=r"(r1),"=r"(r2),"=r"(r3) : "r"(addr))

#define MMA_BF16(c0,c1,c2,c3,a0,a1,a2,a3,b0,b1) \
    asm volatile("mma.sync.aligned.m16n8k16.row.col.f32.bf16.bf16.f32 " \
        "{%0,%1,%2,%3}, {%4,%5,%6,%7}, {%8,%9}, {%0,%1,%2,%3};" \
        : "+f"(c0),"+f"(c1),"+f"(c2),"+f"(c3) \
        : "r"(a0),"r"(a1),"r"(a2),"r"(a3), "r"(b0),"r"(b1))

__device__ __forceinline__ uint32_t smem_u32(const void* p) {
    uint32_t a;
    asm("{ .reg .u64 t; cvta.to.shared.u64 t, %1; cvt.u32.u64 %0, t; }" : "=r"(a) : "l"(p));
    return a;
}

// ---------------- K1: row reductions over A -> moc, dp -------------------
__global__ void __launch_bounds__(256) k_reduce(const float* __restrict__ A)
{
    int bx = blockIdx.x;            // bx = n*1024 + i
    int n = bx >> 10, i = bx & 1023;
    int w = threadIdx.x >> 5, l = threadIdx.x & 31;
    size_t row = ((size_t)(n*AIN + w) << 20) + ((size_t)i << 10);
    const float4* p = (const float4*)(A + row);
    float s = 0.f;
#pragma unroll
    for (int k = 0; k < 8; ++k) {
        float4 v = p[k*32 + l];
        s += v.x + v.y + v.z + v.w;
    }
#pragma unroll
    for (int o = 16; o; o >>= 1) s += __shfl_xor_sync(0xffffffffu, s, o);
    if (l == 0) {
        g_moc[(bx << 3) + w] = s * (1.f/1024.f);
        g_dp [(bx << 3) + w] = A[row + i];
    }
}

// ---------------- K_owh (no deps; overlaps k_reduce on s2) -----------------
__global__ void __launch_bounds__(256) k_owh(
    const float* __restrict__ AW1, const float* __restrict__ OW)
{
    int a = blockIdx.x, tid = threadIdx.x;
    __shared__ float sw[AOUT];
    if (tid < AOUT) sw[tid] = AW1[a*AOUT + tid];
    __syncthreads();
    for (int idx = tid; idx < 4096; idx += 256) {
        int u = idx >> 6, t = idx & 63;
        float s = 0.f;
#pragma unroll
        for (int ss = 0; ss < AOUT; ++ss)
            s = fmaf(sw[ss], OW[((ss<<6)+u)*64 + t], s);
        g_OWH[((a<<6)+u)*64 + t] = s;
    }
}

// ---------------- K2a: per-n means + C -----------------------------------
__global__ void __launch_bounds__(1024) k_pre_n(
    const float* __restrict__ X,
    const float* __restrict__ AW2, const float* __restrict__ AW4,
    const float* __restrict__ AW7, const float* __restrict__ Abias)
{
    int n = blockIdx.x, tid = threadIdx.x;
    __shared__ float spart[16][64];
    __shared__ float sdpp[128][8];
    __shared__ float salp[128][8];
    __shared__ float smx[XIN], smdp[AIN], smal[AIN];

    {
        int col = tid & 63, seg = tid >> 6;
        const float* xp = X + ((size_t)n << 16) + (size_t)(seg << 6) * XIN + col;
        float s = 0.f;
#pragma unroll 4
        for (int r = 0; r < 64; ++r) s += xp[(size_t)r * XIN];
        spart[seg][col] = s;
    }
    {
        int a = tid & 7, seg = tid >> 3;
        const float* dpp = g_dp  + (n << 13) + (seg << 6) + a;
        const float* mcp = g_moc + (n << 13) + (seg << 6) + a;
        float s1 = 0.f, s2 = 0.f;
#pragma unroll
        for (int r = 0; r < 8; ++r) { s1 += dpp[r*8]; s2 += mcp[r*8]; }
        sdpp[seg][a] = s1; salp[seg][a] = s2;
    }
    __syncthreads();
    if (tid < 64) {
        float s = 0.f;
#pragma unroll
        for (int k = 0; k < 16; ++k) s += spart[k][tid];
        smx[tid] = s * (1.f/1024.f);
        g_mX[n*XIN + tid] = smx[tid];
    } else if (tid >= 64 && tid < 72) {
        int a = tid - 64; float s = 0.f;
        for (int k = 0; k < 128; ++k) s += sdpp[k][a];
        smdp[a] = s * (1.f/1024.f); g_mdp[n*AIN + a] = smdp[a];
    } else if (tid >= 72 && tid < 80) {
        int a = tid - 72; float s = 0.f;
        for (int k = 0; k < 128; ++k) s += salp[k][a];
        smal[a] = s * (1.f/1024.f); g_mall[n*AIN + a] = smal[a];
    }
    __syncthreads();
    if (tid < AOUT) {
        int s16 = tid; float c = Abias[s16];
#pragma unroll
        for (int a = 0; a < AIN; ++a)
            c = fmaf(smal[a], AW2[a*AOUT+s16], fmaf(smdp[a], AW4[a*AOUT+s16], c));
        for (int k = 0; k < XIN; ++k) c = fmaf(smx[k], AW7[k*AOUT+s16], c);
        g_C[n*AOUT + s16] = c;
    }
}

// ---------------- K_R: R and Rt only (needs k_reduce + X, NOT the means) ---
__global__ void __launch_bounds__(256) k_R(
    const float* __restrict__ X,
    const float* __restrict__ AW3, const float* __restrict__ AW5,
    const float* __restrict__ AW6)
{
    int bx = blockIdx.x;                 // 256 blocks x 16 nodes
    int tid = threadIdx.x;
    int nl = tid >> 4, q = tid & 15;
    int node0 = bx << 4;
    int n = node0 >> 10;
    int node = node0 + nl;

    __shared__ float sx[16][64];
    __shared__ float smoc[16][8], sdpv[16][8];

    {
        const float4* xp = (const float4*)(X + ((size_t)node0 << 6));
        ((float4*)&sx[0][0])[tid] = xp[tid];
    }
    if (tid < 128) {
        ((float*)smoc)[tid] = g_moc[(node0<<3) + tid];
        ((float*)sdpv)[tid] = g_dp [(node0<<3) + tid];
    }
    __syncthreads();

    float r = 0.f;
#pragma unroll
    for (int a = 0; a < AIN; ++a) {
        r = fmaf(smoc[nl][a], AW3[a*AOUT+q], r);
        r = fmaf(sdpv[nl][a], AW5[a*AOUT+q], r);
    }
#pragma unroll 8
    for (int k = 0; k < XIN; ++k) r = fmaf(sx[nl][k], AW6[k*AOUT+q], r);
    g_R [((size_t)node << 4) + q] = r;
    g_Rt[(n << 14) + (q << 10) + (node & 1023)] = r;
}

// ---------------- K2b: per-node X1t, X2t, X2tT (no R; 512 thr) ------------
__global__ void __launch_bounds__(512) k_node2(
    const float* __restrict__ X,
    const float* __restrict__ X1W1, const float* __restrict__ X1W2, const float* __restrict__ X1W3,
    const float* __restrict__ X1W4, const float* __restrict__ X1W5, const float* __restrict__ X1W6,
    const float* __restrict__ X1b,
    const float* __restrict__ X2W1, const float* __restrict__ X2W2, const float* __restrict__ X2W3,
    const float* __restrict__ X2W4, const float* __restrict__ X2W5, const float* __restrict__ X2W6,
    const float* __restrict__ X2b)
{
    int bx = blockIdx.x;                 // 256 blocks x 16 nodes
    int tid = threadIdx.x;
    int nl = tid >> 5, q = tid & 31, t0 = q << 1;   // 2 t-cols per lane
    int node0 = bx << 4;
    int n = node0 >> 10;
    int node = node0 + nl;

    __shared__ float sx[16][64];
    __shared__ float smoc[16][8], sdpv[16][8];
    __shared__ float smx[64], smdp[8], smal[8];

    if (tid < 256) {
        const float4* xp = (const float4*)(X + ((size_t)node0 << 6));
        ((float4*)&sx[0][0])[tid] = xp[tid];
    } else if (tid < 384) {
        int k = tid - 256;
        ((float*)smoc)[k] = g_moc[(node0<<3) + k];
        ((float*)sdpv)[k] = g_dp [(node0<<3) + k];
    } else if (tid < 448) {
        smx[tid-384] = g_mX[(n<<6) + tid-384];
    } else if (tid < 456) {
        smdp[tid-448] = g_mdp[(n<<3) + tid-448];
    } else if (tid < 464) {
        smal[tid-456] = g_mall[(n<<3) + tid-456];
    }
    __syncthreads();

    float2 b1 = *(const float2*)(X1b + t0);
    float2 b2 = *(const float2*)(X2b + t0);
    ULL x1acc, x2acc;
    PACKXY(x1acc, b1.x, b1.y);
    PACKXY(x2acc, b2.x, b2.y);

#pragma unroll 8
    for (int k = 0; k < XIN; ++k) {
        float xk = sx[nl][k], mk = smx[k];
        ULL xkp, mkp; PACK2(xkp, xk); PACK2(mkp, mk);
        float2 w; ULL wp;
        w = *(const float2*)(X1W1 + (k<<6) + t0);
        PACKXY(wp, w.x, w.y); FMA2(x1acc, xkp, wp);
        w = *(const float2*)(X2W1 + (k<<6) + t0);
        PACKXY(wp, w.x, w.y); FMA2(x2acc, xkp, wp);
        w = *(const float2*)(X1W2 + (k<<6) + t0);
        PACKXY(wp, w.x, w.y); FMA2(x1acc, mkp, wp);
        w = *(const float2*)(X2W2 + (k<<6) + t0);
        PACKXY(wp, w.x, w.y); FMA2(x2acc, mkp, wp);
    }
#pragma unroll
    for (int a = 0; a < AIN; ++a) {
        ULL v1, v2, v3, v4;
        PACK2(v1, smoc[nl][a]); PACK2(v2, sdpv[nl][a]);
        PACK2(v3, smdp[a]);     PACK2(v4, smal[a]);
        float2 w; ULL wp;
        w = *(const float2*)(X1W3 + (a<<6) + t0);
        PACKXY(wp, w.x, w.y); FMA2(x1acc, v1, wp);
        w = *(const float2*)(X2W3 + (a<<6) + t0);
        PACKXY(wp, w.x, w.y); FMA2(x2acc, v1, wp);
        w = *(const float2*)(X1W4 + (a<<6) + t0);
        PACKXY(wp, w.x, w.y); FMA2(x1acc, v2, wp);
        w = *(const float2*)(X2W4 + (a<<6) + t0);
        PACKXY(wp, w.x, w.y); FMA2(x2acc, v2, wp);
        w = *(const float2*)(X1W5 + (a<<6) + t0);
        PACKXY(wp, w.x, w.y); FMA2(x1acc, v3, wp);
        w = *(const float2*)(X2W5 + (a<<6) + t0);
        PACKXY(wp, w.x, w.y); FMA2(x2acc, v3, wp);
        w = *(const float2*)(X1W6 + (a<<6) + t0);
        PACKXY(wp, w.x, w.y); FMA2(x1acc, v4, wp);
        w = *(const float2*)(X2W6 + (a<<6) + t0);
        PACKXY(wp, w.x, w.y); FMA2(x2acc, v4, wp);
    }
    {
        float2 o1, o2;
        UNPACK2(o1.x, o1.y, x1acc);
        UNPACK2(o2.x, o2.y, x2acc);
        *(float2*)(g_X1t + ((size_t)node << 6) + t0) = o1;
        *(float2*)(g_X2t + ((size_t)node << 6) + t0) = o2;
        int jn = node & 1023;
        float v[2] = {o2.x, o2.y};
#pragma unroll
        for (int d = 0; d < 2; ++d) {
            __nv_bfloat16 h = __float2bfloat16_rn(v[d]);
            __nv_bfloat16 lo = __float2bfloat16_rn(v[d] - __bfloat162float(h));
            g_X2tT_hi[(n<<16) + ((t0+d)<<10) + jn] = h;
            g_X2tT_lo[(n<<16) + ((t0+d)<<10) + jn] = lo;
        }
    }
}

// ---------------- K_q: Q and SX2 partials ---------------------------------
__global__ void __launch_bounds__(1024) k_q()
{
    int bx = blockIdx.x;               // n*16 + seg
    int n = bx >> 4, seg = bx & 15;
    int tid = threadIdx.x;
    int s16 = tid >> 6, t = tid & 63;
    const float* rp = g_R   + ((size_t)n << 10) * AOUT + (size_t)(seg << 6) * AOUT;
    const float* xp = g_X2t + ((size_t)n << 10) * XOUT + (size_t)(seg << 6) * XOUT;
    float q = 0.f;
#pragma unroll 4
    for (int jj = 0; jj < 64; ++jj)
        q = fmaf(rp[jj*AOUT + s16], xp[jj*XOUT + t], q);
    g_Qpart[(size_t)bx * 1024 + tid] = q;
    if (tid < 64) {
        float s = 0.f;
#pragma unroll 4
        for (int jj = 0; jj < 64; ++jj) s += xp[jj*XOUT + tid];
        g_SX2part[bx*64 + tid] = s;
    }
}

// ---------------- K_fin: T, K ---------------------------------------------
__global__ void __launch_bounds__(1024) k_fin(
    const float* __restrict__ OW, const float* __restrict__ outb)
{
    int n = blockIdx.x, tid = threadIdx.x;
    __shared__ float sx2[XOUT];
    __shared__ float sq[AOUT*XOUT];
    __shared__ float st_[AOUT*XOUT];
    __shared__ float sp[AOUT*XOUT];
    {
        float q = 0.f;
#pragma unroll
        for (int seg = 0; seg < 16; ++seg)
            q += g_Qpart[(size_t)((n<<4)|seg) * 1024 + tid];
        sq[tid] = q;
    }
    if (tid < 64) {
        float s = 0.f;
#pragma unroll
        for (int seg = 0; seg < 16; ++seg) s += g_SX2part[((n<<4)|seg)*64 + tid];
        sx2[tid] = s;
    }
    __syncthreads();
    int s16 = tid >> 6, t = tid & 63;
    {
        float v = 0.f;
#pragma unroll 4
        for (int u = 0; u < 64; ++u)
            v = fmaf(sx2[u], OW[((s16<<6)+u)*64 + t], v);
        st_[tid] = v;
        g_T[n*1024 + tid] = v;
    }
    {
        float p = 0.f;
#pragma unroll 4
        for (int u = 0; u < 64; ++u)
            p = fmaf(sq[(s16<<6)+u], OW[(((s16<<6)+u)<<6) + t], p);
        sp[tid] = p;
    }
    __syncthreads();
    if (tid < 64) {
        int tt = tid;
        float qo = 0.f, ct = 0.f;
#pragma unroll
        for (int s = 0; s < AOUT; ++s) {
            qo += sp[(s<<6) + tt];
            ct = fmaf(g_C[n*AOUT + s], st_[(s<<6) + tt], ct);
        }
        g_K[n*XOUT + tt] = (ct + qo) * (1.f/1024.f) + outb[tt];
    }
}

// ---------------- K_h: H GEMM, mma.sync bf16 split, 4 warps x (32i x 32t) --
#define AP 72           // row pitch in bf16 (144 B)
__global__ void __launch_bounds__(128) k_h(const float* __restrict__ A)
{
    __shared__ __align__(16) __nv_bfloat16 sAhi[64*AP], sAlo[64*AP];
    __shared__ __align__(16) __nv_bfloat16 sBhi[64*AP], sBlo[64*AP];
    uint32_t bAhi = smem_u32(sAhi), bAlo = smem_u32(sAlo);
    uint32_t bBhi = smem_u32(sBhi), bBlo = smem_u32(sBlo);

    int bx = blockIdx.x;
    int n = bx >> 7, a = (bx >> 4) & 7, mt = bx & 15;
    int tid = threadIdx.x, w = tid >> 5, l = tid & 31;

    int arow0 = tid >> 4, au = tid & 15;
    int brow0 = tid >> 3, bu = tid & 7;

    const float* Ab = A + ((size_t)((n<<3) + a) << 20) + ((size_t)(mt << 6) << 10);
    const __nv_bfloat16* Bh = g_X2tT_hi + ((size_t)n << 16);
    const __nv_bfloat16* Bl = g_X2tT_lo + ((size_t)n << 16);

    float c[2][4][4];
#pragma unroll
    for (int mi = 0; mi < 2; ++mi)
#pragma unroll
        for (int nt = 0; nt < 4; ++nt)
#pragma unroll
            for (int d = 0; d < 4; ++d) c[mi][nt][d] = 0.f;

    int blk = l >> 3, r8 = l & 7;
    int wi = w >> 1, wt = w & 1;
    uint32_t aoff[2], boff[2];
#pragma unroll
    for (int mi = 0; mi < 2; ++mi)
        aoff[mi] = (uint32_t)((((wi << 5) + (mi << 4) + ((blk & 1) << 3) + r8) * (AP*2))
                              + ((blk >> 1) << 4));
#pragma unroll
    for (int bg = 0; bg < 2; ++bg)
        boff[bg] = (uint32_t)((((wt << 5) + (bg << 4) + ((blk >> 1) << 3) + r8) * (AP*2))
                              + ((blk & 1) << 4));

#pragma unroll 1
    for (int ch = 0; ch < 16; ++ch) {
#pragma unroll
        for (int k = 0; k < 8; ++k) {
            int row = arow0 + (k << 3);
            float4 v = *(const float4*)(Ab + ((size_t)row << 10) + (ch << 6) + (au << 2));
            __nv_bfloat162 h0 = __floats2bfloat162_rn(v.x, v.y);
            __nv_bfloat162 h1 = __floats2bfloat162_rn(v.z, v.w);
            __nv_bfloat162 l0 = __floats2bfloat162_rn(v.x - __bfloat162float(h0.x),
                                                      v.y - __bfloat162float(h0.y));
            __nv_bfloat162 l1 = __floats2bfloat162_rn(v.z - __bfloat162float(h1.x),
                                                      v.w - __bfloat162float(h1.y));
            uint32_t off = row*AP + (au << 2);
            *(__nv_bfloat162*)(sAhi + off)     = h0;
            *(__nv_bfloat162*)(sAhi + off + 2) = h1;
            *(__nv_bfloat162*)(sAlo + off)     = l0;
            *(__nv_bfloat162*)(sAlo + off + 2) = l1;
        }
#pragma unroll
        for (int k = 0; k < 4; ++k) {
            int trow = brow0 + (k << 4);
            uint32_t off = trow*AP + (bu << 3);
            *(uint4*)(sBhi + off) = *(const uint4*)(Bh + ((size_t)trow << 10) + (ch << 6) + (bu << 3));
            *(uint4*)(sBlo + off) = *(const uint4*)(Bl + ((size_t)trow << 10) + (ch << 6) + (bu << 3));
        }
        __syncthreads();

#pragma unroll
        for (int kt = 0; kt < 4; ++kt) {
            uint32_t ah[2][4], al_[2][4], bhf[2][4], blf[2][4];
#pragma unroll
            for (int mi = 0; mi < 2; ++mi) {
                LDSM_X4(ah[mi][0],ah[mi][1],ah[mi][2],ah[mi][3], bAhi + aoff[mi] + (kt << 5));
                LDSM_X4(al_[mi][0],al_[mi][1],al_[mi][2],al_[mi][3], bAlo + aoff[mi] + (kt << 5));
            }
#pragma unroll
            for (int bg = 0; bg < 2; ++bg) {
                LDSM_X4(bhf[bg][0],bhf[bg][1],bhf[bg][2],bhf[bg][3], bBhi + boff[bg] + (kt << 5));
                LDSM_X4(blf[bg][0],blf[bg][1],blf[bg][2],blf[bg][3], bBlo + boff[bg] + (kt << 5));
            }
#pragma unroll
            for (int mi = 0; mi < 2; ++mi)
#pragma unroll
                for (int bg = 0; bg < 2; ++bg)
#pragma unroll
                    for (int hf = 0; hf < 2; ++hf) {
                        int nt = (bg << 1) + hf;
                        uint32_t b0h = bhf[bg][2*hf], b1h = bhf[bg][2*hf+1];
                        uint32_t b0l = blf[bg][2*hf], b1l = blf[bg][2*hf+1];
                        MMA_BF16(c[mi][nt][0],c[mi][nt][1],c[mi][nt][2],c[mi][nt][3],
                                 ah[mi][0],ah[mi][1],ah[mi][2],ah[mi][3], b0h,b1h);
                        MMA_BF16(c[mi][nt][0],c[mi][nt][1],c[mi][nt][2],c[mi][nt][3],
                                 ah[mi][0],ah[mi][1],ah[mi][2],ah[mi][3], b0l,b1l);
                        MMA_BF16(c[mi][nt][0],c[mi][nt][1],c[mi][nt][2],c[mi][nt][3],
                                 al_[mi][0],al_[mi][1],al_[mi][2],al_[mi][3], b0h,b1h);
                    }
        }
        __syncthreads();
    }

    {
        int lr = l >> 2, tc = (l & 3) << 1;
        size_t nb = ((size_t)n << 10);
#pragma unroll
        for (int mi = 0; mi < 2; ++mi) {
            int row0 = (mt << 6) + (wi << 5) + (mi << 4) + lr;
            float* H0 = g_H + ((nb + row0)     << 9) + (a << 6);
            float* H1 = g_H + ((nb + row0 + 8) << 9) + (a << 6);
#pragma unroll
            for (int nt = 0; nt < 4; ++nt) {
                int t = (wt << 5) + (nt << 3) + tc;
                *(float2*)(H0 + t) = make_float2(c[mi][nt][0], c[mi][nt][1]);
                *(float2*)(H1 + t) = make_float2(c[mi][nt][2], c[mi][nt][3]);
            }
        }
    }
}

// ---------------- K3: main — Phase A only, destaged (no smem A) ------------
__global__ void __launch_bounds__(256) k_main(
    const float* __restrict__ A, const float* __restrict__ AW1,
    float* __restrict__ outAt)
{
    __shared__ float sW1[128];
    __shared__ float sC16[16];

    int bx = blockIdx.x;                  // n*1024 + i
    int n = bx >> 10, i = bx & 1023;
    int tid = threadIdx.x;

    if (tid < 128) sW1[tid] = AW1[tid];
    if (tid < AOUT)
        sC16[tid] = g_R[((size_t)bx << 4) + tid] + g_C[(n<<4) + tid];
    __syncthreads();

    int j0 = tid << 2;
    ULL apk[8][2];
    {
        const float* Abase = A + (((size_t)(n<<3)) << 20) + ((size_t)i << 10) + j0;
#pragma unroll
        for (int a = 0; a < AIN; ++a) {
            const ULL* rp = (const ULL*)(Abase + ((size_t)a << 20));
            apk[a][0] = rp[0]; apk[a][1] = rp[1];
        }
    }
    size_t obase = (((size_t)(n<<4)) << 20) + ((size_t)i << 10) + j0;
    const float* Rtb = g_Rt + (n << 14) + j0;
#pragma unroll
    for (int sg = 0; sg < 4; ++sg) {
        float4 c4 = *(const float4*)(sC16 + (sg<<2));
        ULL a0a,a0b,a1a,a1b,a2a,a2b,a3a,a3b;
        PACK2(a0a, c4.x); a0b = a0a;
        PACK2(a1a, c4.y); a1b = a1a;
        PACK2(a2a, c4.z); a2b = a2a;
        PACK2(a3a, c4.w); a3b = a3a;
#pragma unroll
        for (int a = 0; a < AIN; ++a) {
            float4 w4 = *(const float4*)(sW1 + (a<<4) + (sg<<2));
            ULL ws;
            PACK2(ws, w4.x); FMA2(a0a, apk[a][0], ws); FMA2(a0b, apk[a][1], ws);
            PACK2(ws, w4.y); FMA2(a1a, apk[a][0], ws); FMA2(a1b, apk[a][1], ws);
            PACK2(ws, w4.z); FMA2(a2a, apk[a][0], ws); FMA2(a2b, apk[a][1], ws);
            PACK2(ws, w4.w); FMA2(a3a, apk[a][0], ws); FMA2(a3b, apk[a][1], ws);
        }
        float4 rt0 = *(const float4*)(Rtb + (((sg<<2)+0) << 10));
        float4 rt1 = *(const float4*)(Rtb + (((sg<<2)+1) << 10));
        float4 rt2 = *(const float4*)(Rtb + (((sg<<2)+2) << 10));
        float4 rt3 = *(const float4*)(Rtb + (((sg<<2)+3) << 10));
        float v0,v1,v2,v3; float4 o;
        UNPACK2(v0,v1,a0a); UNPACK2(v2,v3,a0b);
        o.x=v0+rt0.x; o.y=v1+rt0.y; o.z=v2+rt0.z; o.w=v3+rt0.w;
        *(float4*)(outAt + obase + (((size_t)((sg<<2)+0)) << 20)) = o;
        UNPACK2(v0,v1,a1a); UNPACK2(v2,v3,a1b);
        o.x=v0+rt1.x; o.y=v1+rt1.y; o.z=v2+rt1.z; o.w=v3+rt1.w;
        *(float4*)(outAt + obase + (((size_t)((sg<<2)+1)) << 20)) = o;
        UNPACK2(v0,v1,a2a); UNPACK2(v2,v3,a2b);
        o.x=v0+rt2.x; o.y=v1+rt2.y; o.z=v2+rt2.z; o.w=v3+rt2.w;
        *(float4*)(outAt + obase + (((size_t)((sg<<2)+2)) << 20)) = o;
        UNPACK2(v0,v1,a3a); UNPACK2(v2,v3,a3b);
        o.x=v0+rt3.x; o.y=v1+rt3.y; o.z=v2+rt3.z; o.w=v3+rt3.w;
        *(float4*)(outAt + obase + (((size_t)((sg<<2)+3)) << 20)) = o;
    }
}

// ---------------- K4: out = H*OWH/n + R*T/n + K + X1t ---------------------
#define SMEM_OUT ((512*64 + 16*512) * 4)

__global__ void __launch_bounds__(256) k_out(float* __restrict__ out2)
{
    extern __shared__ float dyn[];
    float* sOWH = dyn;            // 32768 floats
    float* sH   = dyn + 32768;    // 8192 floats
    int bx = blockIdx.x;          // 256 blocks x 16 nodes
    int n = bx >> 6, tid = threadIdx.x;
    {
        const float4* s4 = (const float4*)g_OWH;
        float4* d4 = (float4*)sOWH;
#pragma unroll
        for (int k = 0; k < 32; ++k) d4[(k<<8)+tid] = s4[(k<<8)+tid];
        const float4* h4 = (const float4*)(g_H + ((size_t)bx << 13));
        float4* dh = (float4*)sH;
#pragma unroll
        for (int k = 0; k < 8; ++k) dh[(k<<8)+tid] = h4[(k<<8)+tid];
    }
    __syncthreads();
    int r = tid >> 4, q = tid & 15, t0 = q << 2;
    int node = (bx << 4) + r;
    ULL acc01 = 0ull, acc23 = 0ull;
    const float* hrow = sH + (r << 9);
#pragma unroll 4
    for (int au = 0; au < 512; ++au) {
        ULL hs; PACK2(hs, hrow[au]);
        const ULL* wr = (const ULL*)(sOWH + (au << 6) + t0);
        FMA2(acc01, hs, wr[0]); FMA2(acc23, hs, wr[1]);
    }
    float a0,a1,a2,a3;
    UNPACK2(a0,a1,acc01); UNPACK2(a2,a3,acc23);
    const float* Tn = g_T + (n << 10);
    const float* Rn = g_R + ((size_t)node << 4);
#pragma unroll
    for (int s = 0; s < AOUT; ++s) {
        float rv = Rn[s];
        float4 tv = *(const float4*)(Tn + (s << 6) + t0);
        a0 = fmaf(rv, tv.x, a0); a1 = fmaf(rv, tv.y, a1);
        a2 = fmaf(rv, tv.z, a2); a3 = fmaf(rv, tv.w, a3);
    }
    const float sc = 1.f/1024.f;
    size_t ob = ((size_t)node << 6) + t0;
    float4 kv  = *(const float4*)(g_K + (n << 6) + t0);
    float4 x1v = *(const float4*)(g_X1t + ob);
    float4 o;
    o.x = a0*sc + kv.x + x1v.x;  o.y = a1*sc + kv.y + x1v.y;
    o.z = a2*sc + kv.z + x1v.z;  o.w = a3*sc + kv.w + x1v.w;
    *(float4*)(out2 + ob) = o;
}

// ---------------- launch ---------------------------------------------------
extern "C" void kernel_launch(void* const* d_in, const int* in_sizes, int n_in,
                              void* d_out, int out_size)
{
    const float* A     = (const float*)d_in[0];
    const float* X     = (const float*)d_in[1];
    const float* AW1   = (const float*)d_in[2];
    const float* AW2   = (const float*)d_in[3];
    const float* AW3   = (const float*)d_in[4];
    const float* AW4   = (const float*)d_in[5];
    const float* AW5   = (const float*)d_in[6];
    const float* AW6   = (const float*)d_in[7];
    const float* AW7   = (const float*)d_in[8];
    const float* Abias = (const float*)d_in[9];
    const float* X1W1  = (const float*)d_in[10];
    const float* X1W2  = (const float*)d_in[11];
    const float* X1W3  = (const float*)d_in[12];
    const float* X1W4  = (const float*)d_in[13];
    const float* X1W5  = (const float*)d_in[14];
    const float* X1W6  = (const float*)d_in[15];
    const float* X1b   = (const float*)d_in[16];
    const float* X2W1  = (const float*)d_in[17];
    const float* X2W2  = (const float*)d_in[18];
    const float* X2W3  = (const float*)d_in[19];
    const float* X2W4  = (const float*)d_in[20];
    const float* X2W5  = (const float*)d_in[21];
    const float* X2W6  = (const float*)d_in[22];
    const float* X2b   = (const float*)d_in[23];
    const float* OW    = (const float*)d_in[24];
    const float* outb  = (const float*)d_in[25];

    float* outAt = (float*)d_out;
    float* out2  = outAt + (size_t)NB * AOUT * NN * NN;

    cudaFuncSetAttribute(k_out, cudaFuncAttributeMaxDynamicSharedMemorySize, SMEM_OUT);

    // ONE auxiliary stream (proven safe); three events.
    // main: k_reduce -> k_pre_n -> [eFork] -> k_R -> [eR] -> k_main
    // s2:   k_owh -> wait eFork -> k_node2 -> k_h -> wait eR -> k_q -> k_fin -> [eJoin]
    cudaStream_t s2;
    cudaStreamCreateWithFlags(&s2, cudaStreamNonBlocking);
    cudaEvent_t eFork, eR, eJoin;
    cudaEventCreateWithFlags(&eFork, cudaEventDisableTiming);
    cudaEventCreateWithFlags(&eR,    cudaEventDisableTiming);
    cudaEventCreateWithFlags(&eJoin, cudaEventDisableTiming);

    k_owh <<<AIN, 256, 0, s2>>>(AW1, OW);      // free overlap with k_reduce
    k_reduce<<<NB*NN, 256>>>(A);
    k_pre_n <<<NB, 1024>>>(X, AW2, AW4, AW7, Abias);
    cudaEventRecord(eFork, 0);
    cudaStreamWaitEvent(s2, eFork, 0);

    // main stream: R (tiny) then the DRAM-bound At construction
    k_R   <<<NB*NN/16, 256>>>(X, AW3, AW5, AW6);
    cudaEventRecord(eR, 0);
    k_main<<<NB*NN, 256>>>(A, AW1, outAt);

    // side stream: node transforms, tensor GEMM, epilogue prep
    k_node2<<<NB*NN/16, 512, 0, s2>>>(X,
                            X1W1, X1W2, X1W3, X1W4, X1W5, X1W6, X1b,
                            X2W1, X2W2, X2W3, X2W4, X2W5, X2W6, X2b);
    k_h   <<<NB*AIN*16, 128, 0, s2>>>(A);
    cudaStreamWaitEvent(s2, eR, 0);
    k_q   <<<NB*16, 1024, 0, s2>>>();
    k_fin <<<NB, 1024, 0, s2>>>(OW, outb);
    cudaEventRecord(eJoin, s2);

    cudaStreamWaitEvent(0, eJoin, 0);
    k_out <<<NB*NN/16, 256, SMEM_OUT>>>(out2);
}

// round 17
// speedup vs baseline: 1.0649x; 1.0649x over previous
#include <cuda_runtime.h>
#include <cuda_bf16.h>
#include <cstdint>

#define NB 4
#define NN 1024
#define AIN 8
#define AOUT 16
#define XIN 64
#define XOUT 64

typedef unsigned long long ULL;

// ---------------- scratch (device globals; no allocation) ----------------
__device__ float g_moc[NB*NN*AIN];
__device__ float g_dp [NB*NN*AIN];
__device__ float g_mdp[NB*AIN];
__device__ float g_mall[NB*AIN];
__device__ float g_mX [NB*XIN];
__device__ float g_C  [NB*AOUT];
__device__ float g_R  [NB*NN*AOUT];
__device__ float g_Rt [NB*AOUT*NN];      // R transposed: [n][s][j]
__device__ float g_X1t[NB*NN*XOUT];
__device__ float g_X2t[NB*NN*XOUT];
__device__ __align__(16) __nv_bfloat16 g_X2tT_hi[NB*XOUT*NN];   // [n][t][j]
__device__ __align__(16) __nv_bfloat16 g_X2tT_lo[NB*XOUT*NN];   // [n][t][j]
__device__ float g_T  [NB*AOUT*XOUT];
__device__ float g_K  [NB*XOUT];
__device__ float g_OWH[AIN*XOUT*XOUT];
__device__ __align__(16) float g_H[NB*NN*AIN*XOUT];
__device__ float g_Qpart[NB*16*AOUT*XOUT];
__device__ float g_SX2part[NB*16*XOUT];

#define FMA2(d,a,b) asm("fma.rn.f32x2 %0, %1, %2, %0;" : "+l"(d) : "l"(a), "l"(b))
#define PACK2(d,x)  asm("mov.b64 %0, {%1, %1};" : "=l"(d) : "f"(x))
#define PACKXY(d,x,y) asm("mov.b64 %0, {%1, %2};" : "=l"(d) : "f"(x), "f"(y))
#define UNPACK2(lo,hi,d) asm("mov.b64 {%0, %1}, %2;" : "=f"(lo), "=f"(hi) : "l"(d))

#define LDSM_X4(r0,r1,r2,r3,addr) \
    asm volatile("ldmatrix.sync.aligned.m8n8.x4.shared.b16 {%0,%1,%2,%3}, [%4];" \
        : "=r"(r0),"=r"(r1),"=r"(r2),"=r"(r3) : "r"(addr))

#define MMA_BF16(c0,c1,c2,c3,a0,a1,a2,a3,b0,b1) \
    asm volatile("mma.sync.aligned.m16n8k16.row.col.f32.bf16.bf16.f32 " \
        "{%0,%1,%2,%3}, {%4,%5,%6,%7}, {%8,%9}, {%0,%1,%2,%3};" \
        : "+f"(c0),"+f"(c1),"+f"(c2),"+f"(c3) \
        : "r"(a0),"r"(a1),"r"(a2),"r"(a3), "r"(b0),"r"(b1))

__device__ __forceinline__ uint32_t smem_u32(const void* p) {
    uint32_t a;
    asm("{ .reg .u64 t; cvta.to.shared.u64 t, %1; cvt.u32.u64 %0, t; }" : "=r"(a) : "l"(p));
    return a;
}

// ---------------- K1: row reductions over A -> moc, dp -------------------
__global__ void __launch_bounds__(256) k_reduce(const float* __restrict__ A)
{
    int bx = blockIdx.x;            // bx = n*1024 + i
    int n = bx >> 10, i = bx & 1023;
    int w = threadIdx.x >> 5, l = threadIdx.x & 31;
    size_t row = ((size_t)(n*AIN + w) << 20) + ((size_t)i << 10);
    const float4* p = (const float4*)(A + row);
    float s = 0.f;
#pragma unroll
    for (int k = 0; k < 8; ++k) {
        float4 v = p[k*32 + l];
        s += v.x + v.y + v.z + v.w;
    }
#pragma unroll
    for (int o = 16; o; o >>= 1) s += __shfl_xor_sync(0xffffffffu, s, o);
    if (l == 0) {
        g_moc[(bx << 3) + w] = s * (1.f/1024.f);
        g_dp [(bx << 3) + w] = A[row + i];
    }
}

// ---------------- K_owh (no deps; overlaps k_reduce on s2) -----------------
__global__ void __launch_bounds__(256) k_owh(
    const float* __restrict__ AW1, const float* __restrict__ OW)
{
    int a = blockIdx.x, tid = threadIdx.x;
    __shared__ float sw[AOUT];
    if (tid < AOUT) sw[tid] = AW1[a*AOUT + tid];
    __syncthreads();
    for (int idx = tid; idx < 4096; idx += 256) {
        int u = idx >> 6, t = idx & 63;
        float s = 0.f;
#pragma unroll
        for (int ss = 0; ss < AOUT; ++ss)
            s = fmaf(sw[ss], OW[((ss<<6)+u)*64 + t], s);
        g_OWH[((a<<6)+u)*64 + t] = s;
    }
}

// ---------------- K2a: per-n means + C -----------------------------------
__global__ void __launch_bounds__(1024) k_pre_n(
    const float* __restrict__ X,
    const float* __restrict__ AW2, const float* __restrict__ AW4,
    const float* __restrict__ AW7, const float* __restrict__ Abias)
{
    int n = blockIdx.x, tid = threadIdx.x;
    __shared__ float spart[16][64];
    __shared__ float sdpp[128][8];
    __shared__ float salp[128][8];
    __shared__ float smx[XIN], smdp[AIN], smal[AIN];

    {
        int col = tid & 63, seg = tid >> 6;
        const float* xp = X + ((size_t)n << 16) + (size_t)(seg << 6) * XIN + col;
        float s = 0.f;
#pragma unroll 4
        for (int r = 0; r < 64; ++r) s += xp[(size_t)r * XIN];
        spart[seg][col] = s;
    }
    {
        int a = tid & 7, seg = tid >> 3;
        const float* dpp = g_dp  + (n << 13) + (seg << 6) + a;
        const float* mcp = g_moc + (n << 13) + (seg << 6) + a;
        float s1 = 0.f, s2 = 0.f;
#pragma unroll
        for (int r = 0; r < 8; ++r) { s1 += dpp[r*8]; s2 += mcp[r*8]; }
        sdpp[seg][a] = s1; salp[seg][a] = s2;
    }
    __syncthreads();
    if (tid < 64) {
        float s = 0.f;
#pragma unroll
        for (int k = 0; k < 16; ++k) s += spart[k][tid];
        smx[tid] = s * (1.f/1024.f);
        g_mX[n*XIN + tid] = smx[tid];
    } else if (tid >= 64 && tid < 72) {
        int a = tid - 64; float s = 0.f;
        for (int k = 0; k < 128; ++k) s += sdpp[k][a];
        smdp[a] = s * (1.f/1024.f); g_mdp[n*AIN + a] = smdp[a];
    } else if (tid >= 72 && tid < 80) {
        int a = tid - 72; float s = 0.f;
        for (int k = 0; k < 128; ++k) s += salp[k][a];
        smal[a] = s * (1.f/1024.f); g_mall[n*AIN + a] = smal[a];
    }
    __syncthreads();
    if (tid < AOUT) {
        int s16 = tid; float c = Abias[s16];
#pragma unroll
        for (int a = 0; a < AIN; ++a)
            c = fmaf(smal[a], AW2[a*AOUT+s16], fmaf(smdp[a], AW4[a*AOUT+s16], c));
        for (int k = 0; k < XIN; ++k) c = fmaf(smx[k], AW7[k*AOUT+s16], c);
        g_C[n*AOUT + s16] = c;
    }
}

// ---------------- K2b: per-node R, X1t, X2t (16 nodes, 512 thr, 2t/lane) --
__global__ void __launch_bounds__(512) k_node(
    const float* __restrict__ X,
    const float* __restrict__ AW3, const float* __restrict__ AW5, const float* __restrict__ AW6,
    const float* __restrict__ X1W1, const float* __restrict__ X1W2, const float* __restrict__ X1W3,
    const float* __restrict__ X1W4, const float* __restrict__ X1W5, const float* __restrict__ X1W6,
    const float* __restrict__ X1b,
    const float* __restrict__ X2W1, const float* __restrict__ X2W2, const float* __restrict__ X2W3,
    const float* __restrict__ X2W4, const float* __restrict__ X2W5, const float* __restrict__ X2W6,
    const float* __restrict__ X2b)
{
    int bx = blockIdx.x;                 // 256 blocks x 16 nodes
    int tid = threadIdx.x;
    int nl = tid >> 5, q = tid & 31, t0 = q << 1;   // 2 t-cols per lane
    int node0 = bx << 4;
    int n = node0 >> 10;
    int node = node0 + nl;

    __shared__ float sx[16][64];
    __shared__ float smoc[16][8], sdpv[16][8];
    __shared__ float smx[64], smdp[8], smal[8];

    if (tid < 256) {
        const float4* xp = (const float4*)(X + ((size_t)node0 << 6));
        ((float4*)&sx[0][0])[tid] = xp[tid];
    } else if (tid < 384) {
        int k = tid - 256;
        ((float*)smoc)[k] = g_moc[(node0<<3) + k];
        ((float*)sdpv)[k] = g_dp [(node0<<3) + k];
    } else if (tid < 448) {
        smx[tid-384] = g_mX[(n<<6) + tid-384];
    } else if (tid < 456) {
        smdp[tid-448] = g_mdp[(n<<3) + tid-448];
    } else if (tid < 464) {
        smal[tid-456] = g_mall[(n<<3) + tid-456];
    }
    __syncthreads();

    float2 b1 = *(const float2*)(X1b + t0);
    float2 b2 = *(const float2*)(X2b + t0);
    ULL x1acc, x2acc;
    PACKXY(x1acc, b1.x, b1.y);
    PACKXY(x2acc, b2.x, b2.y);

#pragma unroll 8
    for (int k = 0; k < XIN; ++k) {
        float xk = sx[nl][k], mk = smx[k];
        ULL xkp, mkp; PACK2(xkp, xk); PACK2(mkp, mk);
        float2 w; ULL wp;
        w = *(const float2*)(X1W1 + (k<<6) + t0);
        PACKXY(wp, w.x, w.y); FMA2(x1acc, xkp, wp);
        w = *(const float2*)(X2W1 + (k<<6) + t0);
        PACKXY(wp, w.x, w.y); FMA2(x2acc, xkp, wp);
        w = *(const float2*)(X1W2 + (k<<6) + t0);
        PACKXY(wp, w.x, w.y); FMA2(x1acc, mkp, wp);
        w = *(const float2*)(X2W2 + (k<<6) + t0);
        PACKXY(wp, w.x, w.y); FMA2(x2acc, mkp, wp);
    }
#pragma unroll
    for (int a = 0; a < AIN; ++a) {
        ULL v1, v2, v3, v4;
        PACK2(v1, smoc[nl][a]); PACK2(v2, sdpv[nl][a]);
        PACK2(v3, smdp[a]);     PACK2(v4, smal[a]);
        float2 w; ULL wp;
        w = *(const float2*)(X1W3 + (a<<6) + t0);
        PACKXY(wp, w.x, w.y); FMA2(x1acc, v1, wp);
        w = *(const float2*)(X2W3 + (a<<6) + t0);
        PACKXY(wp, w.x, w.y); FMA2(x2acc, v1, wp);
        w = *(const float2*)(X1W4 + (a<<6) + t0);
        PACKXY(wp, w.x, w.y); FMA2(x1acc, v2, wp);
        w = *(const float2*)(X2W4 + (a<<6) + t0);
        PACKXY(wp, w.x, w.y); FMA2(x2acc, v2, wp);
        w = *(const float2*)(X1W5 + (a<<6) + t0);
        PACKXY(wp, w.x, w.y); FMA2(x1acc, v3, wp);
        w = *(const float2*)(X2W5 + (a<<6) + t0);
        PACKXY(wp, w.x, w.y); FMA2(x2acc, v3, wp);
        w = *(const float2*)(X1W6 + (a<<6) + t0);
        PACKXY(wp, w.x, w.y); FMA2(x1acc, v4, wp);
        w = *(const float2*)(X2W6 + (a<<6) + t0);
        PACKXY(wp, w.x, w.y); FMA2(x2acc, v4, wp);
    }
    {
        float2 o1, o2;
        UNPACK2(o1.x, o1.y, x1acc);
        UNPACK2(o2.x, o2.y, x2acc);
        *(float2*)(g_X1t + ((size_t)node << 6) + t0) = o1;
        *(float2*)(g_X2t + ((size_t)node << 6) + t0) = o2;
        int jn = node & 1023;
        float v[2] = {o2.x, o2.y};
#pragma unroll
        for (int d = 0; d < 2; ++d) {
            __nv_bfloat16 h = __float2bfloat16_rn(v[d]);
            __nv_bfloat16 lo = __float2bfloat16_rn(v[d] - __bfloat162float(h));
            g_X2tT_hi[(n<<16) + ((t0+d)<<10) + jn] = h;
            g_X2tT_lo[(n<<16) + ((t0+d)<<10) + jn] = lo;
        }
    }
    if (q < AOUT) {
        float r = 0.f;
#pragma unroll
        for (int a = 0; a < AIN; ++a) {
            r = fmaf(smoc[nl][a], AW3[a*AOUT+q], r);
            r = fmaf(sdpv[nl][a], AW5[a*AOUT+q], r);
        }
#pragma unroll 8
        for (int k = 0; k < XIN; ++k) r = fmaf(sx[nl][k], AW6[k*AOUT+q], r);
        g_R [((size_t)node << 4) + q] = r;
        g_Rt[(n << 14) + (q << 10) + (node & 1023)] = r;
    }
}

// ---------------- K_q: Q and SX2 partials ---------------------------------
__global__ void __launch_bounds__(1024) k_q()
{
    int bx = blockIdx.x;               // n*16 + seg
    int n = bx >> 4, seg = bx & 15;
    int tid = threadIdx.x;
    int s16 = tid >> 6, t = tid & 63;
    const float* rp = g_R   + ((size_t)n << 10) * AOUT + (size_t)(seg << 6) * AOUT;
    const float* xp = g_X2t + ((size_t)n << 10) * XOUT + (size_t)(seg << 6) * XOUT;
    float q = 0.f;
#pragma unroll 4
    for (int jj = 0; jj < 64; ++jj)
        q = fmaf(rp[jj*AOUT + s16], xp[jj*XOUT + t], q);
    g_Qpart[(size_t)bx * 1024 + tid] = q;
    if (tid < 64) {
        float s = 0.f;
#pragma unroll 4
        for (int jj = 0; jj < 64; ++jj) s += xp[jj*XOUT + tid];
        g_SX2part[bx*64 + tid] = s;
    }
}

// ---------------- K_fin: T, K ---------------------------------------------
__global__ void __launch_bounds__(1024) k_fin(
    const float* __restrict__ OW, const float* __restrict__ outb)
{
    int n = blockIdx.x, tid = threadIdx.x;
    __shared__ float sx2[XOUT];
    __shared__ float sq[AOUT*XOUT];
    __shared__ float st_[AOUT*XOUT];
    __shared__ float sp[AOUT*XOUT];
    {
        float q = 0.f;
#pragma unroll
        for (int seg = 0; seg < 16; ++seg)
            q += g_Qpart[(size_t)((n<<4)|seg) * 1024 + tid];
        sq[tid] = q;
    }
    if (tid < 64) {
        float s = 0.f;
#pragma unroll
        for (int seg = 0; seg < 16; ++seg) s += g_SX2part[((n<<4)|seg)*64 + tid];
        sx2[tid] = s;
    }
    __syncthreads();
    int s16 = tid >> 6, t = tid & 63;
    {
        float v = 0.f;
#pragma unroll 4
        for (int u = 0; u < 64; ++u)
            v = fmaf(sx2[u], OW[((s16<<6)+u)*64 + t], v);
        st_[tid] = v;
        g_T[n*1024 + tid] = v;
    }
    {
        float p = 0.f;
#pragma unroll 4
        for (int u = 0; u < 64; ++u)
            p = fmaf(sq[(s16<<6)+u], OW[(((s16<<6)+u)<<6) + t], p);
        sp[tid] = p;
    }
    __syncthreads();
    if (tid < 64) {
        int tt = tid;
        float qo = 0.f, ct = 0.f;
#pragma unroll
        for (int s = 0; s < AOUT; ++s) {
            qo += sp[(s<<6) + tt];
            ct = fmaf(g_C[n*AOUT + s], st_[(s<<6) + tt], ct);
        }
        g_K[n*XOUT + tt] = (ct + qo) * (1.f/1024.f) + outb[tt];
    }
}

// ---------------- K_h: H GEMM, mma.sync bf16 split, 4 warps x (32i x 32t) --
#define AP 72           // row pitch in bf16 (144 B)
__global__ void __launch_bounds__(128) k_h(const float* __restrict__ A)
{
    __shared__ __align__(16) __nv_bfloat16 sAhi[64*AP], sAlo[64*AP];
    __shared__ __align__(16) __nv_bfloat16 sBhi[64*AP], sBlo[64*AP];
    uint32_t bAhi = smem_u32(sAhi), bAlo = smem_u32(sAlo);
    uint32_t bBhi = smem_u32(sBhi), bBlo = smem_u32(sBlo);

    int bx = blockIdx.x;
    int n = bx >> 7, a = (bx >> 4) & 7, mt = bx & 15;
    int tid = threadIdx.x, w = tid >> 5, l = tid & 31;

    int arow0 = tid >> 4, au = tid & 15;
    int brow0 = tid >> 3, bu = tid & 7;

    const float* Ab = A + ((size_t)((n<<3) + a) << 20) + ((size_t)(mt << 6) << 10);
    const __nv_bfloat16* Bh = g_X2tT_hi + ((size_t)n << 16);
    const __nv_bfloat16* Bl = g_X2tT_lo + ((size_t)n << 16);

    float c[2][4][4];
#pragma unroll
    for (int mi = 0; mi < 2; ++mi)
#pragma unroll
        for (int nt = 0; nt < 4; ++nt)
#pragma unroll
            for (int d = 0; d < 4; ++d) c[mi][nt][d] = 0.f;

    int blk = l >> 3, r8 = l & 7;
    int wi = w >> 1, wt = w & 1;
    uint32_t aoff[2], boff[2];
#pragma unroll
    for (int mi = 0; mi < 2; ++mi)
        aoff[mi] = (uint32_t)((((wi << 5) + (mi << 4) + ((blk & 1) << 3) + r8) * (AP*2))
                              + ((blk >> 1) << 4));
#pragma unroll
    for (int bg = 0; bg < 2; ++bg)
        boff[bg] = (uint32_t)((((wt << 5) + (bg << 4) + ((blk >> 1) << 3) + r8) * (AP*2))
                              + ((blk & 1) << 4));

#pragma unroll 1
    for (int ch = 0; ch < 16; ++ch) {
#pragma unroll
        for (int k = 0; k < 8; ++k) {
            int row = arow0 + (k << 3);
            float4 v = *(const float4*)(Ab + ((size_t)row << 10) + (ch << 6) + (au << 2));
            __nv_bfloat162 h0 = __floats2bfloat162_rn(v.x, v.y);
            __nv_bfloat162 h1 = __floats2bfloat162_rn(v.z, v.w);
            __nv_bfloat162 l0 = __floats2bfloat162_rn(v.x - __bfloat162float(h0.x),
                                                      v.y - __bfloat162float(h0.y));
            __nv_bfloat162 l1 = __floats2bfloat162_rn(v.z - __bfloat162float(h1.x),
                                                      v.w - __bfloat162float(h1.y));
            uint32_t off = row*AP + (au << 2);
            *(__nv_bfloat162*)(sAhi + off)     = h0;
            *(__nv_bfloat162*)(sAhi + off + 2) = h1;
            *(__nv_bfloat162*)(sAlo + off)     = l0;
            *(__nv_bfloat162*)(sAlo + off + 2) = l1;
        }
#pragma unroll
        for (int k = 0; k < 4; ++k) {
            int trow = brow0 + (k << 4);
            uint32_t off = trow*AP + (bu << 3);
            *(uint4*)(sBhi + off) = *(const uint4*)(Bh + ((size_t)trow << 10) + (ch << 6) + (bu << 3));
            *(uint4*)(sBlo + off) = *(const uint4*)(Bl + ((size_t)trow << 10) + (ch << 6) + (bu << 3));
        }
        __syncthreads();

#pragma unroll
        for (int kt = 0; kt < 4; ++kt) {
            uint32_t ah[2][4], al_[2][4], bhf[2][4], blf[2][4];
#pragma unroll
            for (int mi = 0; mi < 2; ++mi) {
                LDSM_X4(ah[mi][0],ah[mi][1],ah[mi][2],ah[mi][3], bAhi + aoff[mi] + (kt << 5));
                LDSM_X4(al_[mi][0],al_[mi][1],al_[mi][2],al_[mi][3], bAlo + aoff[mi] + (kt << 5));
            }
#pragma unroll
            for (int bg = 0; bg < 2; ++bg) {
                LDSM_X4(bhf[bg][0],bhf[bg][1],bhf[bg][2],bhf[bg][3], bBhi + boff[bg] + (kt << 5));
                LDSM_X4(blf[bg][0],blf[bg][1],blf[bg][2],blf[bg][3], bBlo + boff[bg] + (kt << 5));
            }
#pragma unroll
            for (int mi = 0; mi < 2; ++mi)
#pragma unroll
                for (int bg = 0; bg < 2; ++bg)
#pragma unroll
                    for (int hf = 0; hf < 2; ++hf) {
                        int nt = (bg << 1) + hf;
                        uint32_t b0h = bhf[bg][2*hf], b1h = bhf[bg][2*hf+1];
                        uint32_t b0l = blf[bg][2*hf], b1l = blf[bg][2*hf+1];
                        MMA_BF16(c[mi][nt][0],c[mi][nt][1],c[mi][nt][2],c[mi][nt][3],
                                 ah[mi][0],ah[mi][1],ah[mi][2],ah[mi][3], b0h,b1h);
                        MMA_BF16(c[mi][nt][0],c[mi][nt][1],c[mi][nt][2],c[mi][nt][3],
                                 ah[mi][0],ah[mi][1],ah[mi][2],ah[mi][3], b0l,b1l);
                        MMA_BF16(c[mi][nt][0],c[mi][nt][1],c[mi][nt][2],c[mi][nt][3],
                                 al_[mi][0],al_[mi][1],al_[mi][2],al_[mi][3], b0h,b1h);
                    }
        }
        __syncthreads();
    }

    {
        int lr = l >> 2, tc = (l & 3) << 1;
        size_t nb = ((size_t)n << 10);
#pragma unroll
        for (int mi = 0; mi < 2; ++mi) {
            int row0 = (mt << 6) + (wi << 5) + (mi << 4) + lr;
            float* H0 = g_H + ((nb + row0)     << 9) + (a << 6);
            float* H1 = g_H + ((nb + row0 + 8) << 9) + (a << 6);
#pragma unroll
            for (int nt = 0; nt < 4; ++nt) {
                int t = (wt << 5) + (nt << 3) + tc;
                *(float2*)(H0 + t) = make_float2(c[mi][nt][0], c[mi][nt][1]);
                *(float2*)(H1 + t) = make_float2(c[mi][nt][2], c[mi][nt][3]);
            }
        }
    }
}

// ---------------- K3: main — Phase A only, destaged (no smem A) ------------
__global__ void __launch_bounds__(256) k_main(
    const float* __restrict__ A, const float* __restrict__ AW1,
    float* __restrict__ outAt)
{
    __shared__ float sW1[128];
    __shared__ float sC16[16];

    int bx = blockIdx.x;                  // n*1024 + i
    int n = bx >> 10, i = bx & 1023;
    int tid = threadIdx.x;

    if (tid < 128) sW1[tid] = AW1[tid];
    if (tid < AOUT)
        sC16[tid] = g_R[((size_t)bx << 4) + tid] + g_C[(n<<4) + tid];
    __syncthreads();

    int j0 = tid << 2;
    ULL apk[8][2];
    {
        const float* Abase = A + (((size_t)(n<<3)) << 20) + ((size_t)i << 10) + j0;
#pragma unroll
        for (int a = 0; a < AIN; ++a) {
            const ULL* rp = (const ULL*)(Abase + ((size_t)a << 20));
            apk[a][0] = rp[0]; apk[a][1] = rp[1];
        }
    }
    size_t obase = (((size_t)(n<<4)) << 20) + ((size_t)i << 10) + j0;
    const float* Rtb = g_Rt + (n << 14) + j0;
#pragma unroll
    for (int sg = 0; sg < 4; ++sg) {
        float4 c4 = *(const float4*)(sC16 + (sg<<2));
        ULL a0a,a0b,a1a,a1b,a2a,a2b,a3a,a3b;
        PACK2(a0a, c4.x); a0b = a0a;
        PACK2(a1a, c4.y); a1b = a1a;
        PACK2(a2a, c4.z); a2b = a2a;
        PACK2(a3a, c4.w); a3b = a3a;
#pragma unroll
        for (int a = 0; a < AIN; ++a) {
            float4 w4 = *(const float4*)(sW1 + (a<<4) + (sg<<2));
            ULL ws;
            PACK2(ws, w4.x); FMA2(a0a, apk[a][0], ws); FMA2(a0b, apk[a][1], ws);
            PACK2(ws, w4.y); FMA2(a1a, apk[a][0], ws); FMA2(a1b, apk[a][1], ws);
            PACK2(ws, w4.z); FMA2(a2a, apk[a][0], ws); FMA2(a2b, apk[a][1], ws);
            PACK2(ws, w4.w); FMA2(a3a, apk[a][0], ws); FMA2(a3b, apk[a][1], ws);
        }
        float4 rt0 = *(const float4*)(Rtb + (((sg<<2)+0) << 10));
        float4 rt1 = *(const float4*)(Rtb + (((sg<<2)+1) << 10));
        float4 rt2 = *(const float4*)(Rtb + (((sg<<2)+2) << 10));
        float4 rt3 = *(const float4*)(Rtb + (((sg<<2)+3) << 10));
        float v0,v1,v2,v3; float4 o;
        UNPACK2(v0,v1,a0a); UNPACK2(v2,v3,a0b);
        o.x=v0+rt0.x; o.y=v1+rt0.y; o.z=v2+rt0.z; o.w=v3+rt0.w;
        *(float4*)(outAt + obase + (((size_t)((sg<<2)+0)) << 20)) = o;
        UNPACK2(v0,v1,a1a); UNPACK2(v2,v3,a1b);
        o.x=v0+rt1.x; o.y=v1+rt1.y; o.z=v2+rt1.z; o.w=v3+rt1.w;
        *(float4*)(outAt + obase + (((size_t)((sg<<2)+1)) << 20)) = o;
        UNPACK2(v0,v1,a2a); UNPACK2(v2,v3,a2b);
        o.x=v0+rt2.x; o.y=v1+rt2.y; o.z=v2+rt2.z; o.w=v3+rt2.w;
        *(float4*)(outAt + obase + (((size_t)((sg<<2)+2)) << 20)) = o;
        UNPACK2(v0,v1,a3a); UNPACK2(v2,v3,a3b);
        o.x=v0+rt3.x; o.y=v1+rt3.y; o.z=v2+rt3.z; o.w=v3+rt3.w;
        *(float4*)(outAt + obase + (((size_t)((sg<<2)+3)) << 20)) = o;
    }
}

// ---------------- K4: out = H*OWH/n + R*T/n + K + X1t ---------------------
#define SMEM_OUT ((512*64 + 16*512) * 4)

__global__ void __launch_bounds__(256) k_out(float* __restrict__ out2)
{
    extern __shared__ float dyn[];
    float* sOWH = dyn;            // 32768 floats
    float* sH   = dyn + 32768;    // 8192 floats
    int bx = blockIdx.x;          // 256 blocks x 16 nodes
    int n = bx >> 6, tid = threadIdx.x;
    {
        const float4* s4 = (const float4*)g_OWH;
        float4* d4 = (float4*)sOWH;
#pragma unroll
        for (int k = 0; k < 32; ++k) d4[(k<<8)+tid] = s4[(k<<8)+tid];
        const float4* h4 = (const float4*)(g_H + ((size_t)bx << 13));
        float4* dh = (float4*)sH;
#pragma unroll
        for (int k = 0; k < 8; ++k) dh[(k<<8)+tid] = h4[(k<<8)+tid];
    }
    __syncthreads();
    int r = tid >> 4, q = tid & 15, t0 = q << 2;
    int node = (bx << 4) + r;
    ULL acc01 = 0ull, acc23 = 0ull;
    const float* hrow = sH + (r << 9);
#pragma unroll 4
    for (int au = 0; au < 512; ++au) {
        ULL hs; PACK2(hs, hrow[au]);
        const ULL* wr = (const ULL*)(sOWH + (au << 6) + t0);
        FMA2(acc01, hs, wr[0]); FMA2(acc23, hs, wr[1]);
    }
    float a0,a1,a2,a3;
    UNPACK2(a0,a1,acc01); UNPACK2(a2,a3,acc23);
    const float* Tn = g_T + (n << 10);
    const float* Rn = g_R + ((size_t)node << 4);
#pragma unroll
    for (int s = 0; s < AOUT; ++s) {
        float rv = Rn[s];
        float4 tv = *(const float4*)(Tn + (s << 6) + t0);
        a0 = fmaf(rv, tv.x, a0); a1 = fmaf(rv, tv.y, a1);
        a2 = fmaf(rv, tv.z, a2); a3 = fmaf(rv, tv.w, a3);
    }
    const float sc = 1.f/1024.f;
    size_t ob = ((size_t)node << 6) + t0;
    float4 kv  = *(const float4*)(g_K + (n << 6) + t0);
    float4 x1v = *(const float4*)(g_X1t + ob);
    float4 o;
    o.x = a0*sc + kv.x + x1v.x;  o.y = a1*sc + kv.y + x1v.y;
    o.z = a2*sc + kv.z + x1v.z;  o.w = a3*sc + kv.w + x1v.w;
    *(float4*)(out2 + ob) = o;
}

// ---------------- launch ---------------------------------------------------
extern "C" void kernel_launch(void* const* d_in, const int* in_sizes, int n_in,
                              void* d_out, int out_size)
{
    const float* A     = (const float*)d_in[0];
    const float* X     = (const float*)d_in[1];
    const float* AW1   = (const float*)d_in[2];
    const float* AW2   = (const float*)d_in[3];
    const float* AW3   = (const float*)d_in[4];
    const float* AW4   = (const float*)d_in[5];
    const float* AW5   = (const float*)d_in[6];
    const float* AW6   = (const float*)d_in[7];
    const float* AW7   = (const float*)d_in[8];
    const float* Abias = (const float*)d_in[9];
    const float* X1W1  = (const float*)d_in[10];
    const float* X1W2  = (const float*)d_in[11];
    const float* X1W3  = (const float*)d_in[12];
    const float* X1W4  = (const float*)d_in[13];
    const float* X1W5  = (const float*)d_in[14];
    const float* X1W6  = (const float*)d_in[15];
    const float* X1b   = (const float*)d_in[16];
    const float* X2W1  = (const float*)d_in[17];
    const float* X2W2  = (const float*)d_in[18];
    const float* X2W3  = (const float*)d_in[19];
    const float* X2W4  = (const float*)d_in[20];
    const float* X2W5  = (const float*)d_in[21];
    const float* X2W6  = (const float*)d_in[22];
    const float* X2b   = (const float*)d_in[23];
    const float* OW    = (const float*)d_in[24];
    const float* outb  = (const float*)d_in[25];

    float* outAt = (float*)d_out;
    float* out2  = outAt + (size_t)NB * AOUT * NN * NN;

    cudaFuncSetAttribute(k_out, cudaFuncAttributeMaxDynamicSharedMemorySize, SMEM_OUT);

    // ONE auxiliary stream (round-15 proven topology). Change vs round 15:
    // k_out moved onto s2 (it reads only s2/pre-fork products: H, OWH, T, K,
    // X1t, R — and writes out2, disjoint from k_main's outAt), so it overlaps
    // k_main's tail instead of serializing after the join.
    cudaStream_t s2;
    cudaStreamCreateWithFlags(&s2, cudaStreamNonBlocking);
    cudaEvent_t eFork, eJoin;
    cudaEventCreateWithFlags(&eFork, cudaEventDisableTiming);
    cudaEventCreateWithFlags(&eJoin, cudaEventDisableTiming);

    k_owh <<<AIN, 256, 0, s2>>>(AW1, OW);      // free overlap with k_reduce
    k_reduce<<<NB*NN, 256>>>(A);
    k_pre_n <<<NB, 1024>>>(X, AW2, AW4, AW7, Abias);
    k_node  <<<NB*NN/16, 512>>>(X, AW3, AW5, AW6,
                            X1W1, X1W2, X1W3, X1W4, X1W5, X1W6, X1b,
                            X2W1, X2W2, X2W3, X2W4, X2W5, X2W6, X2b);
    cudaEventRecord(eFork, 0);
    cudaStreamWaitEvent(s2, eFork, 0);

    // side stream: tensor GEMM + epilogue prep + final small output
    k_h   <<<NB*AIN*16, 128, 0, s2>>>(A);
    k_q   <<<NB*16, 1024, 0, s2>>>();
    k_fin <<<NB, 1024, 0, s2>>>(OW, outb);
    k_out <<<NB*NN/16, 256, SMEM_OUT, s2>>>(out2);
    cudaEventRecord(eJoin, s2);

    // main stream: DRAM-bound At construction, concurrent with s2
    k_main<<<NB*NN, 256>>>(A, AW1, outAt);

    cudaStreamWaitEvent(0, eJoin, 0);
}